// round 1
// baseline (speedup 1.0000x reference)
#include <cuda_runtime.h>
#include <cuda_bf16.h>
#include <stdint.h>

#define K_DIM 2048
#define N_DIM 2048
#define TOPK  1024

// Scratch for masked weights (allocation-free rule: __device__ global)
__device__ float g_wm[(size_t)N_DIM * K_DIM];

// ---------------------------------------------------------------------------
// Kernel 1: per-output-row exact top-k threshold (radix select on |w| bits)
// and masked-weight materialization. One block (256 threads) per row.
// ---------------------------------------------------------------------------
__global__ __launch_bounds__(256) void mask_kernel(const float* __restrict__ w) {
    __shared__ unsigned int bits[K_DIM];
    __shared__ unsigned int hist[256];
    __shared__ unsigned int s_prefix, s_kwant, s_cnt_gt;

    const int row = blockIdx.x;
    const int tid = threadIdx.x;
    const float* wr = w + (size_t)row * K_DIM;

    for (int i = tid; i < K_DIM; i += 256)
        bits[i] = __float_as_uint(wr[i]) & 0x7FFFFFFFu;  // |w| bit pattern (monotone)
    if (tid == 0) { s_cnt_gt = 0; }
    __syncthreads();

    // 4-pass MSB-first radix select: find bits of the TOPK-th largest |w|
    unsigned int prefix = 0;
    unsigned int kwant = TOPK;
    #pragma unroll
    for (int pass = 3; pass >= 0; --pass) {
        const int shift = pass * 8;
        hist[tid] = 0;
        __syncthreads();
        if (pass == 3) {
            for (int i = tid; i < K_DIM; i += 256)
                atomicAdd(&hist[(bits[i] >> shift) & 0xFFu], 1u);
        } else {
            const unsigned int hi_mask = 0xFFFFFFFFu << (shift + 8);
            for (int i = tid; i < K_DIM; i += 256) {
                const unsigned int b = bits[i];
                if ((b & hi_mask) == (prefix & hi_mask))
                    atomicAdd(&hist[(b >> shift) & 0xFFu], 1u);
            }
        }
        __syncthreads();
        if (tid == 0) {
            unsigned int cum = 0;
            int bin = 255;
            for (; bin > 0; --bin) {
                const unsigned int c = hist[bin];
                if (cum + c >= kwant) break;
                cum += c;
            }
            s_prefix = prefix | ((unsigned int)bin << shift);
            s_kwant = kwant - cum;
        }
        __syncthreads();
        prefix = s_prefix;
        kwant  = s_kwant;
        __syncthreads();
    }
    const unsigned int thresh = prefix;

    // Count strictly-greater elements to size the tie budget.
    unsigned int local_gt = 0;
    for (int i = tid; i < K_DIM; i += 256)
        if (bits[i] > thresh) local_gt++;
    atomicAdd(&s_cnt_gt, local_gt);
    __syncthreads();
    const unsigned int need_eq = TOPK - s_cnt_gt;  // ties kept = first by index

    for (int i = tid; i < K_DIM; i += 256) {
        const unsigned int b = bits[i];
        float val = 0.0f;
        if (b > thresh) {
            val = wr[i];
        } else if (b == thresh) {
            // rank among equal elements by index (ties are nearly always 1 elem)
            unsigned int r = 0;
            for (int j = 0; j < i; ++j) r += (bits[j] == thresh);
            if (r < need_eq) val = wr[i];
        }
        g_wm[(size_t)row * K_DIM + i] = val;
    }
}

// ---------------------------------------------------------------------------
// Kernel 2: FP32 SIMT GEMM  y[M,N] = x[M,K] * Wm[N,K]^T + bias
// 128x128x16 block tile, 256 threads, 8x8 per thread.
// ---------------------------------------------------------------------------
#define BM 128
#define BN 128
#define BK 16

__global__ __launch_bounds__(256) void gemm_kernel(const float* __restrict__ x,
                                                   const float* __restrict__ bias,
                                                   float* __restrict__ y) {
    __shared__ float xs[BK][BM + 4];
    __shared__ float ws[BK][BN + 4];

    const int t  = threadIdx.x;
    const int m0 = blockIdx.y * BM;
    const int n0 = blockIdx.x * BN;
    const int tx = t & 15;    // n direction, 16 threads
    const int ty = t >> 4;    // m direction, 16 threads

    float acc[8][8];
    #pragma unroll
    for (int i = 0; i < 8; ++i)
        #pragma unroll
        for (int j = 0; j < 8; ++j) acc[i][j] = 0.0f;

    for (int k0 = 0; k0 < K_DIM; k0 += BK) {
        // Load 128x16 tiles of x and Wm (512 float4 each, 2 per thread)
        #pragma unroll
        for (int u = 0; u < 2; ++u) {
            const int f   = t + u * 256;
            const int row = f >> 2;
            const int c   = (f & 3) * 4;
            const float4 vx = *(const float4*)(x + (size_t)(m0 + row) * K_DIM + k0 + c);
            xs[c + 0][row] = vx.x; xs[c + 1][row] = vx.y;
            xs[c + 2][row] = vx.z; xs[c + 3][row] = vx.w;
            const float4 vw = *(const float4*)(g_wm + (size_t)(n0 + row) * K_DIM + k0 + c);
            ws[c + 0][row] = vw.x; ws[c + 1][row] = vw.y;
            ws[c + 2][row] = vw.z; ws[c + 3][row] = vw.w;
        }
        __syncthreads();

        #pragma unroll
        for (int kk = 0; kk < BK; ++kk) {
            float a[8], b[8];
            #pragma unroll
            for (int i = 0; i < 8; ++i) a[i] = xs[kk][ty * 8 + i];
            #pragma unroll
            for (int j = 0; j < 8; ++j) b[j] = ws[kk][tx * 8 + j];
            #pragma unroll
            for (int i = 0; i < 8; ++i)
                #pragma unroll
                for (int j = 0; j < 8; ++j)
                    acc[i][j] = fmaf(a[i], b[j], acc[i][j]);
        }
        __syncthreads();
    }

    // Epilogue: add bias, vectorized store
    #pragma unroll
    for (int i = 0; i < 8; ++i) {
        const int m = m0 + ty * 8 + i;
        #pragma unroll
        for (int j = 0; j < 8; j += 4) {
            const int n = n0 + tx * 8 + j;
            float4 o;
            o.x = acc[i][j + 0] + bias[n + 0];
            o.y = acc[i][j + 1] + bias[n + 1];
            o.z = acc[i][j + 2] + bias[n + 2];
            o.w = acc[i][j + 3] + bias[n + 3];
            *(float4*)(y + (size_t)m * N_DIM + n) = o;
        }
    }
}

// ---------------------------------------------------------------------------
extern "C" void kernel_launch(void* const* d_in, const int* in_sizes, int n_in,
                              void* d_out, int out_size) {
    const float* x    = (const float*)d_in[0];   // [8,2048,2048]
    const float* w    = (const float*)d_in[1];   // [2048,2048]
    const float* bias = (const float*)d_in[2];   // [2048]
    float* y = (float*)d_out;

    const int M = in_sizes[0] / K_DIM;           // 16384

    mask_kernel<<<N_DIM, 256>>>(w);

    dim3 grid(N_DIM / BN, M / BM);               // (16, 128)
    gemm_kernel<<<grid, 256>>>(x, bias, y);
}

// round 3
// speedup vs baseline: 2.4714x; 2.4714x over previous
#include <cuda_runtime.h>
#include <cuda_bf16.h>
#include <stdint.h>
#include <string.h>

#define K_DIM 2048
#define N_DIM 2048
#define TOPK  1024
#define BM 128
#define BN 128
#define BK 64
#define STAGES 3
#define STAGE_BYTES (2 * BM * BK * 2)   // A tile + B tile, bf16 = 32 KB
#define NITER 96                        // K_eff = 3 * 2048 = 6144 = 96 * 64

// Row-major bf16 scratch (device globals: allocation-free rule)
__device__ __align__(16) __nv_bfloat16 g_Ah[(size_t)16384 * K_DIM];
__device__ __align__(16) __nv_bfloat16 g_Al[(size_t)16384 * K_DIM];
__device__ __align__(16) __nv_bfloat16 g_Bh[(size_t)N_DIM * K_DIM];
__device__ __align__(16) __nv_bfloat16 g_Bl[(size_t)N_DIM * K_DIM];

// ---------------------------------------------------------------------------
// PTX helpers (baseline sm_80+ features only: valid for compute_103 PTX)
// ---------------------------------------------------------------------------
__device__ __forceinline__ uint32_t smem_u32(const void* p) {
    uint32_t a;
    asm("{ .reg .u64 t; cvta.to.shared.u64 t, %1; cvt.u32.u64 %0, t; }" : "=r"(a) : "l"(p));
    return a;
}
__device__ __forceinline__ void cpa16(uint32_t dst, const void* src) {
    asm volatile("cp.async.cg.shared.global [%0], [%1], 16;" :: "r"(dst), "l"(src) : "memory");
}
__device__ __forceinline__ void cpa_commit() {
    asm volatile("cp.async.commit_group;" ::: "memory");
}
__device__ __forceinline__ void cpa_wait1() {
    asm volatile("cp.async.wait_group 1;" ::: "memory");
}
__device__ __forceinline__ void ldsm_x4(uint32_t (&r)[4], uint32_t addr) {
    asm volatile("ldmatrix.sync.aligned.m8n8.x4.shared.b16 {%0,%1,%2,%3}, [%4];"
                 : "=r"(r[0]), "=r"(r[1]), "=r"(r[2]), "=r"(r[3]) : "r"(addr));
}
__device__ __forceinline__ void mma_bf16(float (&c)[4], const uint32_t (&a)[4],
                                         uint32_t b0, uint32_t b1) {
    asm volatile(
        "mma.sync.aligned.m16n8k16.row.col.f32.bf16.bf16.f32 "
        "{%0,%1,%2,%3}, {%4,%5,%6,%7}, {%8,%9}, {%0,%1,%2,%3};"
        : "+f"(c[0]), "+f"(c[1]), "+f"(c[2]), "+f"(c[3])
        : "r"(a[0]), "r"(a[1]), "r"(a[2]), "r"(a[3]), "r"(b0), "r"(b1));
}

// ---------------------------------------------------------------------------
// Kernel 1: per-row exact top-k (radix select on |w| bits) -> wh/wl bf16
// ---------------------------------------------------------------------------
__global__ __launch_bounds__(256) void mask_kernel(const float* __restrict__ w) {
    __shared__ unsigned int bits[K_DIM];
    __shared__ unsigned int hist[256];
    __shared__ unsigned int s_prefix, s_kwant, s_cnt_gt;

    const int row = blockIdx.x;
    const int tid = threadIdx.x;
    const float* wr = w + (size_t)row * K_DIM;

    for (int i = tid; i < K_DIM; i += 256)
        bits[i] = __float_as_uint(wr[i]) & 0x7FFFFFFFu;
    if (tid == 0) s_cnt_gt = 0;
    __syncthreads();

    unsigned int prefix = 0, kwant = TOPK;
    #pragma unroll
    for (int pass = 3; pass >= 0; --pass) {
        const int shift = pass * 8;
        hist[tid] = 0;
        __syncthreads();
        if (pass == 3) {
            for (int i = tid; i < K_DIM; i += 256)
                atomicAdd(&hist[(bits[i] >> shift) & 0xFFu], 1u);
        } else {
            const unsigned int hi_mask = 0xFFFFFFFFu << (shift + 8);
            for (int i = tid; i < K_DIM; i += 256) {
                const unsigned int b = bits[i];
                if ((b & hi_mask) == (prefix & hi_mask))
                    atomicAdd(&hist[(b >> shift) & 0xFFu], 1u);
            }
        }
        __syncthreads();
        if (tid == 0) {
            unsigned int cum = 0;
            int bin = 255;
            for (; bin > 0; --bin) {
                const unsigned int c = hist[bin];
                if (cum + c >= kwant) break;
                cum += c;
            }
            s_prefix = prefix | ((unsigned int)bin << shift);
            s_kwant  = kwant - cum;
        }
        __syncthreads();
        prefix = s_prefix;
        kwant  = s_kwant;
        __syncthreads();
    }
    const unsigned int thresh = prefix;

    unsigned int local_gt = 0;
    for (int i = tid; i < K_DIM; i += 256)
        if (bits[i] > thresh) local_gt++;
    atomicAdd(&s_cnt_gt, local_gt);
    __syncthreads();
    const unsigned int need_eq = TOPK - s_cnt_gt;

    for (int i = tid; i < K_DIM; i += 256) {
        const unsigned int b = bits[i];
        float val = 0.0f;
        if (b > thresh) {
            val = wr[i];
        } else if (b == thresh) {
            unsigned int rr = 0;
            for (int j = 0; j < i; ++j) rr += (bits[j] == thresh);
            if (rr < need_eq) val = wr[i];
        }
        __nv_bfloat16 h = __float2bfloat16_rn(val);
        __nv_bfloat16 l = __float2bfloat16_rn(val - __bfloat162float(h));
        g_Bh[(size_t)row * K_DIM + i] = h;
        g_Bl[(size_t)row * K_DIM + i] = l;
    }
}

// ---------------------------------------------------------------------------
// Kernel 2: x -> (xh, xl) bf16, row-major. Thread handles 8 consecutive k.
// ---------------------------------------------------------------------------
__global__ __launch_bounds__(256) void convert_x(const float* __restrict__ x) {
    const size_t t = (size_t)blockIdx.x * 256 + threadIdx.x;
    const size_t base = t * 8;

    const float4* src = (const float4*)(x + base);
    float4 v0 = src[0], v1 = src[1];
    float v[8] = {v0.x, v0.y, v0.z, v0.w, v1.x, v1.y, v1.z, v1.w};

    uint32_t hp[4], lp[4];
    #pragma unroll
    for (int i = 0; i < 4; ++i) {
        float a = v[2 * i], b = v[2 * i + 1];
        __nv_bfloat162 hh = __floats2bfloat162_rn(a, b);
        float ra = a - __bfloat162float(__low2bfloat16(hh));
        float rb = b - __bfloat162float(__high2bfloat16(hh));
        __nv_bfloat162 ll = __floats2bfloat162_rn(ra, rb);
        memcpy(&hp[i], &hh, 4);
        memcpy(&lp[i], &ll, 4);
    }
    *(uint4*)(g_Ah + base) = make_uint4(hp[0], hp[1], hp[2], hp[3]);
    *(uint4*)(g_Al + base) = make_uint4(lp[0], lp[1], lp[2], lp[3]);
}

// ---------------------------------------------------------------------------
// Kernel 3: pipelined mma.sync bf16 GEMM.
// y[M,N] = sum over K_eff=6144 of A'[M, ke] * B'[N, ke] + bias
//   A' = [xh | xh | xl], B' = [wh | wl | wh]
// 128x128 tile/CTA, 256 thr (2x4 warps of 64x32), 3-stage cp.async pipeline.
// ---------------------------------------------------------------------------
__device__ __forceinline__ void load_stage(uint32_t sbase, int st, int iter,
                                           int m0, int n0, int tid) {
    const int phase = iter >> 5;
    const __nv_bfloat16* aSrc = (phase == 2) ? g_Al : g_Ah;
    const __nv_bfloat16* bSrc = (phase == 1) ? g_Bl : g_Bh;
    const int kc = (iter & 31) * BK;
    const uint32_t sA = sbase + st * STAGE_BYTES;
    const uint32_t sB = sA + BM * BK * 2;

    #pragma unroll
    for (int u = 0; u < 4; ++u) {
        const int f   = tid + u * 256;
        const int row = f >> 3;
        const int ch  = f & 7;
        const uint32_t so = (uint32_t)(row * 8 + (ch ^ (row & 7))) * 16u;
        cpa16(sA + so, aSrc + (size_t)(m0 + row) * K_DIM + kc + ch * 8);
        cpa16(sB + so, bSrc + (size_t)(n0 + row) * K_DIM + kc + ch * 8);
    }
}

__global__ void __launch_bounds__(256, 2) gemm_mma(const float* __restrict__ bias,
                                                   float* __restrict__ y) {
    extern __shared__ unsigned char dyn_smem[];
    const uint32_t sbase = smem_u32(dyn_smem);

    const int tid  = threadIdx.x;
    const int wid  = tid >> 5;
    const int lane = tid & 31;
    const int m_tile = blockIdx.x >> 4;
    const int n_tile = blockIdx.x & 15;
    const int m0 = m_tile * BM;
    const int n0 = n_tile * BN;

    const int wm = wid >> 2;          // 0..1
    const int wn = wid & 3;           // 0..3
    const int lr = lane & 15;         // ldmatrix row within 16
    const int lc = lane >> 4;         // ldmatrix k-chunk selector

    float acc[4][4][4];
    #pragma unroll
    for (int i = 0; i < 4; ++i)
        #pragma unroll
        for (int j = 0; j < 4; ++j)
            #pragma unroll
            for (int r = 0; r < 4; ++r) acc[i][j][r] = 0.0f;

    load_stage(sbase, 0, 0, m0, n0, tid); cpa_commit();
    load_stage(sbase, 1, 1, m0, n0, tid); cpa_commit();

    for (int it = 0; it < NITER; ++it) {
        const int st = it % STAGES;
        cpa_wait1();
        __syncthreads();
        if (it + 2 < NITER) load_stage(sbase, (it + 2) % STAGES, it + 2, m0, n0, tid);
        cpa_commit();

        const uint32_t sA = sbase + st * STAGE_BYTES;
        const uint32_t sB = sA + BM * BK * 2;

        #pragma unroll
        for (int ks = 0; ks < 4; ++ks) {
            const int ch = ks * 2 + lc;
            uint32_t a[4][4], b[2][4];
            #pragma unroll
            for (int ms = 0; ms < 4; ++ms) {
                const int row = wm * 64 + ms * 16 + lr;
                ldsm_x4(a[ms], sA + (uint32_t)(row * 8 + (ch ^ (row & 7))) * 16u);
            }
            #pragma unroll
            for (int bs = 0; bs < 2; ++bs) {
                const int row = wn * 32 + bs * 16 + lr;
                ldsm_x4(b[bs], sB + (uint32_t)(row * 8 + (ch ^ (row & 7))) * 16u);
            }
            #pragma unroll
            for (int ms = 0; ms < 4; ++ms)
                #pragma unroll
                for (int nb = 0; nb < 4; ++nb)
                    mma_bf16(acc[ms][nb], a[ms], b[nb >> 1][nb & 1], b[nb >> 1][2 + (nb & 1)]);
        }
        __syncthreads();
    }

    // Epilogue: bias add + float2 stores
    const int ln4 = lane & 3;
    const int lg  = lane >> 2;
    float2 bv[4];
    #pragma unroll
    for (int nb = 0; nb < 4; ++nb) {
        const int c = n0 + wn * 32 + nb * 8 + ln4 * 2;
        bv[nb].x = __ldg(bias + c);
        bv[nb].y = __ldg(bias + c + 1);
    }
    #pragma unroll
    for (int ms = 0; ms < 4; ++ms) {
        const int r0 = m0 + wm * 64 + ms * 16 + lg;
        #pragma unroll
        for (int nb = 0; nb < 4; ++nb) {
            const int c = n0 + wn * 32 + nb * 8 + ln4 * 2;
            float2 o0, o1;
            o0.x = acc[ms][nb][0] + bv[nb].x;
            o0.y = acc[ms][nb][1] + bv[nb].y;
            o1.x = acc[ms][nb][2] + bv[nb].x;
            o1.y = acc[ms][nb][3] + bv[nb].y;
            *(float2*)(y + (size_t)r0 * N_DIM + c)       = o0;
            *(float2*)(y + (size_t)(r0 + 8) * N_DIM + c) = o1;
        }
    }
}

// ---------------------------------------------------------------------------
extern "C" void kernel_launch(void* const* d_in, const int* in_sizes, int n_in,
                              void* d_out, int out_size) {
    const float* x    = (const float*)d_in[0];   // [8,2048,2048]
    const float* w    = (const float*)d_in[1];   // [2048,2048]
    const float* bias = (const float*)d_in[2];   // [2048]
    float* y = (float*)d_out;

    const int M = in_sizes[0] / K_DIM;           // 16384

    cudaFuncSetAttribute(gemm_mma, cudaFuncAttributeMaxDynamicSharedMemorySize,
                         STAGES * STAGE_BYTES);

    mask_kernel<<<N_DIM, 256>>>(w);
    convert_x<<<(int)(((size_t)M * K_DIM / 8) / 256), 256>>>(x);

    const int grid = (M / BM) * (N_DIM / BN);    // 128 * 16 = 2048
    gemm_mma<<<grid, 256, STAGES * STAGE_BYTES>>>(bias, y);
}